// round 1
// baseline (speedup 1.0000x reference)
#include <cuda_runtime.h>

// ---------------- problem constants ----------------
#define BN   32
#define TN   4096
#define CINN 165
#define CHN  256
#define EDIM 64
#define NEMB 512
#define NTOK (BN*TN)          // 131072
#define TILE 64               // tokens per CTA
#define NBLK (NTOK/TILE)      // 2048
#define LDA  68               // padded token-row stride (floats), 16B aligned
#define DEC_ELEMS (NTOK*CINN) // 21626880

// shared layout (floats): A[256*LDA] | B[256*LDA] | Z[64*LDA] | Ws[32*257]
#define SM_A  0
#define SM_B  (256*LDA)
#define SM_Z  (2*256*LDA)
#define SM_W  (SM_Z + 64*LDA)
#define SM_FLOATS (SM_W + 32*257)
#define SMEM_BYTES (SM_FLOATS*4)

typedef unsigned long long ULL;

__device__ float g_enorm[NEMB];
__device__ float g_part[NBLK];

// ---------------- f32x2 helpers ----------------
__device__ __forceinline__ ULL pack2(float x, float y) {
    ULL r; asm("mov.b64 %0, {%1, %2};" : "=l"(r) : "f"(x), "f"(y)); return r;
}
__device__ __forceinline__ void unpack2(ULL v, float& x, float& y) {
    asm("mov.b64 {%0, %1}, %2;" : "=f"(x), "=f"(y) : "l"(v));
}
__device__ __forceinline__ void fma2(ULL& d, ULL a, ULL b) {
    asm("fma.rn.f32x2 %0, %1, %2, %0;" : "+l"(d) : "l"(a), "l"(b));
}

// ---------------- fused 1x1-conv layer ----------------
// OUT[c][t] = (RES ? OUT[c][t] : 0) + bias[c] + sum_k W[c][k] * (PRE? relu(IN[k][t]) : IN[k][t])
// POST: relu the result. 256 threads: 32 channel-groups x 8 token-groups (8 tokens each).
template<int COUT, int CIN_, bool PRE, bool POST, bool RES>
__device__ __forceinline__ void conv_layer(const float* __restrict__ W,
                                           const float* __restrict__ bias,
                                           const float* __restrict__ IN,
                                           float* __restrict__ OUT,
                                           float* __restrict__ Ws, int tid)
{
    constexpr int MT  = (COUT + 31) >> 5;   // channels per thread
    constexpr int CW  = MT * 32;            // padded channel count
    constexpr int WSP = CW + 1;             // odd row stride -> conflict-free staging
    constexpr int KB  = 32;
    constexpr int NK  = (CIN_ + KB - 1) / KB;

    const int tx = tid & 7;
    const int ty = tid >> 3;
    const int c0 = ty * MT;
    const int j0 = tx * 8;

    ULL acc[MT][4];
#pragma unroll
    for (int m = 0; m < MT; m++)
#pragma unroll
        for (int p = 0; p < 4; p++) acc[m][p] = 0ull;

    for (int kb = 0; kb < NK; kb++) {
        const int k0 = kb * KB;
        __syncthreads();
        // stage W chunk: Ws[kk][c], kk fastest in tid -> coalesced gmem reads,
        // stride-WSP (odd) smem writes -> conflict-free
        constexpr int NLD = (KB * CW) / 256;
#pragma unroll
        for (int i = 0; i < NLD; i++) {
            int idx = i * 256 + tid;
            int kk  = idx & 31;
            int c   = idx >> 5;
            int k   = k0 + kk;
            float v = 0.f;
            if (k < CIN_ && c < COUT) v = __ldg(W + c * CIN_ + k);
            Ws[kk * WSP + c] = v;
        }
        __syncthreads();

#pragma unroll 4
        for (int kk = 0; kk < KB; kk++) {
            const float* inr = IN + (k0 + kk) * LDA + j0;
            float4 va = *reinterpret_cast<const float4*>(inr);
            float4 vb = *reinterpret_cast<const float4*>(inr + 4);
            if (PRE) {
                va.x = fmaxf(va.x, 0.f); va.y = fmaxf(va.y, 0.f);
                va.z = fmaxf(va.z, 0.f); va.w = fmaxf(va.w, 0.f);
                vb.x = fmaxf(vb.x, 0.f); vb.y = fmaxf(vb.y, 0.f);
                vb.z = fmaxf(vb.z, 0.f); vb.w = fmaxf(vb.w, 0.f);
            }
            ULL t0 = pack2(va.x, va.y), t1 = pack2(va.z, va.w);
            ULL t2 = pack2(vb.x, vb.y), t3 = pack2(vb.z, vb.w);
            const float* wr = Ws + kk * WSP + c0;
#pragma unroll
            for (int m = 0; m < MT; m++) {
                float w = wr[m];
                ULL w2 = pack2(w, w);
                fma2(acc[m][0], w2, t0);
                fma2(acc[m][1], w2, t1);
                fma2(acc[m][2], w2, t2);
                fma2(acc[m][3], w2, t3);
            }
        }
    }

    // epilogue
#pragma unroll
    for (int m = 0; m < MT; m++) {
        int c = c0 + m;
        if ((COUT & 31) != 0) { if (c >= COUT) continue; }
        float bv = __ldg(bias + c);
        float r[8];
        unpack2(acc[m][0], r[0], r[1]);
        unpack2(acc[m][1], r[2], r[3]);
        unpack2(acc[m][2], r[4], r[5]);
        unpack2(acc[m][3], r[6], r[7]);
        float* orow = OUT + c * LDA + j0;
#pragma unroll
        for (int n = 0; n < 8; n++) {
            float v = r[n] + bv;
            if (RES)  v += orow[n];
            if (POST) v = fmaxf(v, 0.f);
            orow[n] = v;
        }
    }
}

struct Params { const float* in[32]; float* out; };

// ---------------- aux kernels ----------------
__global__ void enorm_kernel(const float* __restrict__ embed) {
    int k = blockIdx.x * blockDim.x + threadIdx.x;
    if (k < NEMB) {
        float s = 0.f;
        for (int d = 0; d < EDIM; d++) { float e = embed[d * NEMB + k]; s += e * e; }
        g_enorm[k] = s;
    }
}

__global__ void finalize_kernel(float* __restrict__ out, int out_size) {
    __shared__ float sh[256];
    float s = 0.f;
    for (int i = threadIdx.x; i < NBLK; i += 256) s += g_part[i];
    sh[threadIdx.x] = s;
    __syncthreads();
    for (int st = 128; st > 0; st >>= 1) {
        if (threadIdx.x < st) sh[threadIdx.x] += sh[threadIdx.x + st];
        __syncthreads();
    }
    if (threadIdx.x == 0 && out_size > DEC_ELEMS)
        out[DEC_ELEMS] = sh[0] * (1.0f / 8388608.0f);  // mean over N*EDIM
}

// ---------------- main fused kernel ----------------
__global__ void __launch_bounds__(256, 1) vqvae_kernel(Params P)
{
    extern __shared__ float sm[];
    float* A  = sm + SM_A;
    float* Bv = sm + SM_B;
    float* Z  = sm + SM_Z;
    float* Ws = sm + SM_W;

    const int tid = threadIdx.x;
    const int n0  = blockIdx.x * TILE;

    // ---- load x tile, transpose [tok][c] -> [c][tok]; zero-pad rows 165..191 ----
    const float* x = P.in[0];
    for (int idx = tid; idx < 192 * TILE; idx += 256) {
        int c = idx % 192;
        int j = idx / 192;
        float v = 0.f;
        if (c < CINN) v = x[(n0 + j) * CINN + c];
        A[c * LDA + j] = v;
    }
    // (first conv's leading __syncthreads orders this)

    // ---- encoder ----
    conv_layer<128, 165, false, true,  false>(P.in[1],  P.in[2],  A,  Bv, Ws, tid);
    conv_layer<256, 128, false, true,  false>(P.in[3],  P.in[4],  Bv, A,  Ws, tid);
    conv_layer<256, 256, false, false, false>(P.in[5],  P.in[6],  A,  Bv, Ws, tid);
    conv_layer< 32, 256, true,  true,  false>(P.in[7],  P.in[8],  Bv, A,  Ws, tid);
    conv_layer<256,  32, false, false, true >(P.in[9],  P.in[10], A,  Bv, Ws, tid);
    conv_layer< 32, 256, true,  true,  false>(P.in[11], P.in[12], Bv, A,  Ws, tid);
    conv_layer<256,  32, false, false, true >(P.in[13], P.in[14], A,  Bv, Ws, tid);
    conv_layer< 64, 256, true,  false, false>(P.in[15], P.in[16], Bv, Z,  Ws, tid);

    // ---- vector quantize ----
    {
        const float* embed = P.in[17];
        float* Es = Ws;                 // [64][68]
        float* en = Ws + 64 * 68;       // [64]
        const int j = tid >> 2;         // token 0..63
        const int q = tid & 3;          // code-quarter
        float best = 3.4e38f; int bidx = 0;

        for (int cb = 0; cb < 8; cb++) {
            __syncthreads();
#pragma unroll
            for (int i = 0; i < 16; i++) {
                int idx = i * 256 + tid;
                int kk = idx & 63, d = idx >> 6;
                Es[d * 68 + kk] = __ldg(embed + d * NEMB + cb * 64 + kk);
            }
            if (tid < 64) en[tid] = g_enorm[cb * 64 + tid];
            __syncthreads();

            ULL dot[8];
#pragma unroll
            for (int g = 0; g < 8; g++) dot[g] = 0ull;
            const float* zc = Z + j;
#pragma unroll 4
            for (int d = 0; d < EDIM; d++) {
                float z = zc[d * LDA];
                ULL z2 = pack2(z, z);
                const float* er = Es + d * 68 + q * 16;
#pragma unroll
                for (int g2 = 0; g2 < 4; g2++) {
                    ulonglong2 ee = *reinterpret_cast<const ulonglong2*>(er + g2 * 4);
                    fma2(dot[2 * g2],     z2, ee.x);
                    fma2(dot[2 * g2 + 1], z2, ee.y);
                }
            }
#pragma unroll
            for (int g = 0; g < 8; g++) {
                float d0, d1; unpack2(dot[g], d0, d1);
                int kbase = cb * 64 + q * 16 + 2 * g;
                float s0 = en[q * 16 + 2 * g]     - 2.f * d0;
                float s1 = en[q * 16 + 2 * g + 1] - 2.f * d1;
                if (s0 < best) { best = s0; bidx = kbase; }
                if (s1 < best) { best = s1; bidx = kbase + 1; }
            }
        }
        // argmin across the 4 lanes of this token (tie -> lower index, matches argmin)
#pragma unroll
        for (int off = 1; off < 4; off <<= 1) {
            float ob = __shfl_xor_sync(0xffffffffu, best, off);
            int   oi = __shfl_xor_sync(0xffffffffu, bidx, off);
            if (ob < best || (ob == best && oi < bidx)) { best = ob; bidx = oi; }
        }
        // gather codebook vector into A, accumulate diff partial
        float dsum = 0.f;
#pragma unroll
        for (int dd = 0; dd < 16; dd++) {
            int d = q * 16 + dd;
            float e = __ldg(embed + d * NEMB + bidx);
            float z = Z[d * LDA + j];
            A[d * LDA + j] = e;
            float df = e - z;
            dsum += df * df;
        }
#pragma unroll
        for (int off = 16; off > 0; off >>= 1)
            dsum += __shfl_xor_sync(0xffffffffu, dsum, off);
        __shared__ float wsum[8];
        if ((tid & 31) == 0) wsum[tid >> 5] = dsum;
        __syncthreads();
        if (tid == 0) {
            float s = 0.f;
#pragma unroll
            for (int w = 0; w < 8; w++) s += wsum[w];
            g_part[blockIdx.x] = s;
        }
    }

    // ---- decoder ----
    conv_layer<256,  64, false, false, false>(P.in[18], P.in[19], A,  Bv, Ws, tid);
    conv_layer< 32, 256, true,  true,  false>(P.in[20], P.in[21], Bv, A,  Ws, tid);
    conv_layer<256,  32, false, false, true >(P.in[22], P.in[23], A,  Bv, Ws, tid);
    conv_layer< 32, 256, true,  true,  false>(P.in[24], P.in[25], Bv, A,  Ws, tid);
    conv_layer<256,  32, false, false, true >(P.in[26], P.in[27], A,  Bv, Ws, tid);
    conv_layer<128, 256, true,  true,  false>(P.in[28], P.in[29], Bv, A,  Ws, tid);
    conv_layer<165, 128, false, false, false>(P.in[30], P.in[31], A,  Bv, Ws, tid);
    __syncthreads();

    // ---- store output tile: [c][tok] -> [tok][c], coalesced in c ----
    for (int idx = tid; idx < CINN * TILE; idx += 256) {
        int j = idx / CINN;
        int c = idx - j * CINN;
        P.out[(n0 + j) * CINN + c] = Bv[c * LDA + j];
    }
}

// ---------------- launch ----------------
extern "C" void kernel_launch(void* const* d_in, const int* in_sizes, int n_in,
                              void* d_out, int out_size)
{
    (void)in_sizes; (void)n_in;
    Params P;
    for (int i = 0; i < 32; i++) P.in[i] = (const float*)d_in[i];
    P.out = (float*)d_out;

    cudaFuncSetAttribute(vqvae_kernel, cudaFuncAttributeMaxDynamicSharedMemorySize, SMEM_BYTES);

    enorm_kernel<<<2, 256>>>((const float*)d_in[17]);
    vqvae_kernel<<<NBLK, 256, SMEM_BYTES>>>(P);
    finalize_kernel<<<1, 256>>>((float*)d_out, out_size);
}

// round 2
// speedup vs baseline: 1.1654x; 1.1654x over previous
#include <cuda_runtime.h>
#include <cstdint>

// ---------------- problem constants ----------------
#define BN   32
#define TN   4096
#define CINN 165
#define EDIM 64
#define NEMB 512
#define NTOK (BN*TN)          // 131072
#define TILE 64               // tokens per CTA
#define NBLK (NTOK/TILE)      // 2048
#define LDA  68               // padded token-row stride (floats)
#define DEC_ELEMS (NTOK*CINN) // 21626880
#define THREADS 512

// shared layout (floats)
#define SM_A  0
#define SM_B  (256*LDA)            // 17408
#define SM_Z  (2*256*LDA)          // 34816
#define SM_W  (SM_Z + EDIM*LDA)    // 39168
#define WBUF  8192                 // floats per weight staging buffer (8 groups x 256 ch x 4)
#define SM_AUX (SM_W + 2*WBUF)     // 55552
#define SM_FLOATS (SM_AUX + 512 + 64 + 32)
#define SMEM_BYTES (SM_FLOATS*4)   // ~224.7 KB

typedef unsigned long long ULL;

__device__ float g_part[NBLK];
__device__ unsigned int g_count;

// ---------------- f32x2 helpers ----------------
__device__ __forceinline__ ULL pack2(float x, float y) {
    ULL r; asm("mov.b64 %0, {%1, %2};" : "=l"(r) : "f"(x), "f"(y)); return r;
}
__device__ __forceinline__ void unpack2(ULL v, float& x, float& y) {
    asm("mov.b64 {%0, %1}, %2;" : "=f"(x), "=f"(y) : "l"(v));
}
__device__ __forceinline__ void fma2(ULL& d, ULL a, ULL b) {
    asm("fma.rn.f32x2 %0, %1, %2, %0;" : "+l"(d) : "l"(a), "l"(b));
}
__device__ __forceinline__ uint32_t smem_u32(const void* p) {
    uint32_t a;
    asm("{ .reg .u64 t; cvta.to.shared.u64 t, %1; cvt.u32.u64 %0, t; }" : "=r"(a) : "l"(p));
    return a;
}
__device__ __forceinline__ void cp_async16(uint32_t dst, const void* src, bool full) {
    int sz = full ? 16 : 0;
    asm volatile("cp.async.cg.shared.global [%0], [%1], 16, %2;\n"
                 :: "r"(dst), "l"(src), "r"(sz));
}

// ---------------- weight chunk staging ----------------
// Layout: Ws[buf][g][c] as float4 = W[c][k0+4g .. k0+4g+3], g in [0,8), c in [0,CW)
template<int COUT, int CIN_, int CW, bool ASYNC>
__device__ __forceinline__ void stage_chunk(const float* __restrict__ W,
                                            float* __restrict__ Ws,
                                            int kb, int buf, int tid)
{
    const int k0 = kb * 32;
    if (ASYNC) {
        float4* dst = reinterpret_cast<float4*>(Ws + buf * WBUF);
        constexpr int NCPY = 8 * CW;   // float4 count
        for (int idx = tid; idx < NCPY; idx += THREADS) {
            int g = idx / CW;
            int c = idx - g * CW;
            bool ok = ((COUT & 31) == 0) || (c < COUT);
            const float* src = W + (ok ? (c * CIN_ + k0 + g * 4) : 0);
            cp_async16(smem_u32(dst + idx), src, ok);
        }
        asm volatile("cp.async.commit_group;\n" ::: "memory");
    } else {
        float* dst = Ws + buf * WBUF;
        for (int idx = tid; idx < 8 * CW * 4; idx += THREADS) {
            int g = idx / (CW * 4);
            int rem = idx - g * (CW * 4);
            int c = rem >> 2;
            int r = rem & 3;
            int k = k0 + g * 4 + r;
            float v = 0.f;
            if (k < CIN_ && c < COUT) v = __ldg(W + c * CIN_ + k);
            dst[(g * CW + c) * 4 + r] = v;
        }
    }
}

// ---------------- fused 1x1-conv layer ----------------
// OUT[c][t] = (RES? OUT[c][t]:0) + bias[c] + sum_k W[c][k] * (PRE? relu(IN[k][t]) : IN[k][t])
// 512 threads: 32 channel-groups (MT ch each) x 16 token-groups (4 tokens each)
template<int COUT, int CIN_, bool PRE, bool POST, bool RES, bool ASYNC>
__device__ __noinline__ void conv_layer(const float* __restrict__ W,
                                        const float* __restrict__ bias,
                                        const float* __restrict__ IN,
                                        float* __restrict__ OUT,
                                        float* __restrict__ Ws, int tid)
{
    constexpr int MT = (COUT + 31) >> 5;
    constexpr int CW = MT * 32;
    constexpr int NK = (CIN_ + 31) / 32;

    const int tx = tid & 15;
    const int ty = tid >> 4;
    const int j0 = tx * 4;
    const int c0 = ty * MT;

    float bv[MT];
#pragma unroll
    for (int m = 0; m < MT; m++) {
        int c = c0 + m;
        bv[m] = (((COUT & 31) == 0) || c < COUT) ? __ldg(bias + c) : 0.f;
    }

    ULL acc[MT][2];
#pragma unroll
    for (int m = 0; m < MT; m++) { acc[m][0] = 0ull; acc[m][1] = 0ull; }

    __syncthreads();   // prev-layer activations visible; Ws free
    stage_chunk<COUT, CIN_, CW, ASYNC>(W, Ws, 0, 0, tid);

    for (int kb = 0; kb < NK; kb++) {
        if (ASYNC) asm volatile("cp.async.wait_group 0;\n" ::: "memory");
        __syncthreads();                       // chunk kb staged for all threads
        if (kb + 1 < NK)
            stage_chunk<COUT, CIN_, CW, ASYNC>(W, Ws, kb + 1, (kb + 1) & 1, tid);

        const int k0 = kb * 32;
        const float4* Wq = reinterpret_cast<const float4*>(Ws + (kb & 1) * WBUF);
        const float* inb = IN + k0 * LDA + j0;

#pragma unroll 4
        for (int g = 0; g < 8; g++) {
            ULL t[4][2];
#pragma unroll
            for (int r = 0; r < 4; r++) {
                float4 v = *reinterpret_cast<const float4*>(inb + (g * 4 + r) * LDA);
                if (PRE) {
                    v.x = fmaxf(v.x, 0.f); v.y = fmaxf(v.y, 0.f);
                    v.z = fmaxf(v.z, 0.f); v.w = fmaxf(v.w, 0.f);
                }
                t[r][0] = pack2(v.x, v.y);
                t[r][1] = pack2(v.z, v.w);
            }
#pragma unroll
            for (int m = 0; m < MT; m++) {
                float4 wv = Wq[g * CW + c0 + m];
                ULL w;
                w = pack2(wv.x, wv.x); fma2(acc[m][0], w, t[0][0]); fma2(acc[m][1], w, t[0][1]);
                w = pack2(wv.y, wv.y); fma2(acc[m][0], w, t[1][0]); fma2(acc[m][1], w, t[1][1]);
                w = pack2(wv.z, wv.z); fma2(acc[m][0], w, t[2][0]); fma2(acc[m][1], w, t[2][1]);
                w = pack2(wv.w, wv.w); fma2(acc[m][0], w, t[3][0]); fma2(acc[m][1], w, t[3][1]);
            }
        }
    }

    // epilogue (no sync needed: OUT disjoint from IN/Ws, rows owned exclusively)
#pragma unroll
    for (int m = 0; m < MT; m++) {
        int c = c0 + m;
        if ((COUT & 31) != 0 && c >= COUT) continue;
        float r0, r1, r2, r3;
        unpack2(acc[m][0], r0, r1);
        unpack2(acc[m][1], r2, r3);
        float4 v;
        v.x = r0 + bv[m]; v.y = r1 + bv[m]; v.z = r2 + bv[m]; v.w = r3 + bv[m];
        float* op = OUT + c * LDA + j0;
        if (RES) {
            float4 o = *reinterpret_cast<float4*>(op);
            v.x += o.x; v.y += o.y; v.z += o.z; v.w += o.w;
        }
        if (POST) {
            v.x = fmaxf(v.x, 0.f); v.y = fmaxf(v.y, 0.f);
            v.z = fmaxf(v.z, 0.f); v.w = fmaxf(v.w, 0.f);
        }
        *reinterpret_cast<float4*>(op) = v;
    }
}

struct Params { const float* in[32]; float* out; int out_size; };

// ---------------- main fused kernel ----------------
__global__ void __launch_bounds__(THREADS, 1) vqvae_kernel(Params P)
{
    extern __shared__ float sm[];
    float* A   = sm + SM_A;
    float* Bv  = sm + SM_B;
    float* Z   = sm + SM_Z;
    float* Ws  = sm + SM_W;
    float* enp = sm + SM_AUX;
    float* en  = enp + 512;
    float* wsum = en + 64;

    const int tid = threadIdx.x;
    const int n0  = blockIdx.x * TILE;

    // ---- load x tile, transpose [tok][c] -> [c][tok]; zero-pad rows 165..191 ----
    const float* x = P.in[0];
    for (int idx = tid; idx < 192 * TILE; idx += THREADS) {
        int c = idx % 192;
        int j = idx / 192;
        A[c * LDA + j] = (c < CINN) ? x[(n0 + j) * CINN + c] : 0.f;
    }

    // ---- encoder ----
    conv_layer<128, 165, false, true,  false, false>(P.in[1],  P.in[2],  A,  Bv, Ws, tid);
    conv_layer<256, 128, false, true,  false, true >(P.in[3],  P.in[4],  Bv, A,  Ws, tid);
    conv_layer<256, 256, false, false, false, true >(P.in[5],  P.in[6],  A,  Bv, Ws, tid);
    conv_layer< 32, 256, true,  true,  false, true >(P.in[7],  P.in[8],  Bv, A,  Ws, tid);
    conv_layer<256,  32, false, false, true,  true >(P.in[9],  P.in[10], A,  Bv, Ws, tid);
    conv_layer< 32, 256, true,  true,  false, true >(P.in[11], P.in[12], Bv, A,  Ws, tid);
    conv_layer<256,  32, false, false, true,  true >(P.in[13], P.in[14], A,  Bv, Ws, tid);
    conv_layer< 64, 256, true,  false, false, true >(P.in[15], P.in[16], Bv, Z,  Ws, tid);

    // ---- vector quantize (codebook norms computed in-block) ----
    {
        const float* embed = P.in[17];
        float* Es = Ws;                 // [64 d][64 codes]
        const int j = tid >> 3;         // token 0..63
        const int q = tid & 7;          // code octet within 64-code block
        float best = 3.4e38f; int bidx = 0;

        for (int cb = 0; cb < 8; cb++) {
            __syncthreads();            // Es/en free (everyone past previous use)
            float sq = 0.f;
#pragma unroll
            for (int i = 0; i < 8; i++) {
                int idx = i * THREADS + tid;
                int kk = idx & 63, d = idx >> 6;
                float v = __ldg(embed + d * NEMB + cb * 64 + kk);
                Es[d * 64 + kk] = v;
                sq += v * v;            // all 8 values share kk = tid&63
            }
            enp[tid] = sq;
            __syncthreads();
            if (tid < 64) {
                float s = 0.f;
#pragma unroll
                for (int i = 0; i < 8; i++) s += enp[tid + 64 * i];
                en[tid] = s;
            }
            __syncthreads();

            ULL dot[4] = {0ull, 0ull, 0ull, 0ull};
#pragma unroll 8
            for (int d = 0; d < EDIM; d++) {
                float z = Z[d * LDA + j];
                ULL z2 = pack2(z, z);
                const ulonglong2* er = reinterpret_cast<const ulonglong2*>(Es + d * 64 + q * 8);
                ulonglong2 e0 = er[0], e1 = er[1];
                fma2(dot[0], z2, e0.x); fma2(dot[1], z2, e0.y);
                fma2(dot[2], z2, e1.x); fma2(dot[3], z2, e1.y);
            }
#pragma unroll
            for (int g = 0; g < 4; g++) {
                float d0, d1; unpack2(dot[g], d0, d1);
                int kb = cb * 64 + q * 8 + 2 * g;
                float s0 = en[q * 8 + 2 * g]     - 2.f * d0;
                float s1 = en[q * 8 + 2 * g + 1] - 2.f * d1;
                if (s0 < best) { best = s0; bidx = kb; }
                if (s1 < best) { best = s1; bidx = kb + 1; }
            }
        }
        // argmin across the 8 lanes of this token (tie -> lower index)
#pragma unroll
        for (int off = 1; off < 8; off <<= 1) {
            float ob = __shfl_xor_sync(0xffffffffu, best, off);
            int   oi = __shfl_xor_sync(0xffffffffu, bidx, off);
            if (ob < best || (ob == best && oi < bidx)) { best = ob; bidx = oi; }
        }
        // gather codebook vector into A, accumulate diff partial
        float dsum = 0.f;
#pragma unroll
        for (int dd = 0; dd < 8; dd++) {
            int d = q * 8 + dd;
            float e = __ldg(embed + d * NEMB + bidx);
            float z = Z[d * LDA + j];
            A[d * LDA + j] = e;
            float df = e - z;
            dsum += df * df;
        }
#pragma unroll
        for (int off = 16; off > 0; off >>= 1)
            dsum += __shfl_xor_sync(0xffffffffu, dsum, off);
        if ((tid & 31) == 0) wsum[tid >> 5] = dsum;
        __syncthreads();
        if (tid == 0) {
            float s = 0.f;
#pragma unroll
            for (int w = 0; w < 16; w++) s += wsum[w];
            g_part[blockIdx.x] = s;
        }
    }

    // ---- decoder ----
    conv_layer<256,  64, false, false, false, true >(P.in[18], P.in[19], A,  Bv, Ws, tid);
    conv_layer< 32, 256, true,  true,  false, true >(P.in[20], P.in[21], Bv, A,  Ws, tid);
    conv_layer<256,  32, false, false, true,  true >(P.in[22], P.in[23], A,  Bv, Ws, tid);
    conv_layer< 32, 256, true,  true,  false, true >(P.in[24], P.in[25], Bv, A,  Ws, tid);
    conv_layer<256,  32, false, false, true,  true >(P.in[26], P.in[27], A,  Bv, Ws, tid);
    conv_layer<128, 256, true,  true,  false, true >(P.in[28], P.in[29], Bv, A,  Ws, tid);
    conv_layer<165, 128, false, false, false, true >(P.in[30], P.in[31], A,  Bv, Ws, tid);
    __syncthreads();

    // ---- store output tile: [c][tok] -> [tok][c] ----
    for (int idx = tid; idx < CINN * TILE; idx += THREADS) {
        int j = idx / CINN;
        int c = idx - j * CINN;
        P.out[(n0 + j) * CINN + c] = Bv[c * LDA + j];
    }

    // ---- last-block finalize of diff ----
    __threadfence();
    __shared__ unsigned int is_last;
    if (tid == 0) is_last = (atomicAdd(&g_count, 1u) == NBLK - 1) ? 1u : 0u;
    __syncthreads();
    if (is_last) {
        float s = 0.f;
        for (int i = tid; i < NBLK; i += THREADS) s += g_part[i];
#pragma unroll
        for (int off = 16; off > 0; off >>= 1)
            s += __shfl_xor_sync(0xffffffffu, s, off);
        if ((tid & 31) == 0) wsum[tid >> 5] = s;
        __syncthreads();
        if (tid == 0) {
            float t = 0.f;
#pragma unroll
            for (int w = 0; w < 16; w++) t += wsum[w];
            if (P.out_size > DEC_ELEMS)
                P.out[DEC_ELEMS] = t * (1.0f / 8388608.0f);  // mean over N*EDIM
            g_count = 0u;   // reset for next graph replay
        }
    }
}

// ---------------- launch ----------------
extern "C" void kernel_launch(void* const* d_in, const int* in_sizes, int n_in,
                              void* d_out, int out_size)
{
    (void)in_sizes; (void)n_in;
    Params P;
    for (int i = 0; i < 32; i++) P.in[i] = (const float*)d_in[i];
    P.out = (float*)d_out;
    P.out_size = out_size;

    static bool attr_set = false;
    if (!attr_set) {
        cudaFuncSetAttribute(vqvae_kernel, cudaFuncAttributeMaxDynamicSharedMemorySize, SMEM_BYTES);
        attr_set = true;
    }
    vqvae_kernel<<<NBLK, THREADS, SMEM_BYTES>>>(P);
}

// round 4
// speedup vs baseline: 1.3819x; 1.1858x over previous
#include <cuda_runtime.h>
#include <cstdint>

// ---------------- problem constants ----------------
#define BN   32
#define TN   4096
#define CINN 165
#define EDIM 64
#define NEMB 512
#define NTOK (BN*TN)          // 131072
#define TILE 32               // tokens per CTA
#define NBLK (NTOK/TILE)      // 4096
#define LDA  36               // padded token-row stride (floats)
#define DEC_ELEMS (NTOK*CINN) // 21626880
#define THREADS 256
#define KB 16                 // k per chunk

// shared layout (floats)
#define SM_A   0
#define SM_B   (256*LDA)            // 9216
#define SM_W   (2*256*LDA)          // 18432
#define WBUFF  4096                 // floats per weight buffer (16k x 256c max)
#define SM_AUX (SM_W + 2*WBUFF)     // 26624
#define SM_FLOATS (SM_AUX + 256 + 64 + 16)
#define SMEM_BYTES (SM_FLOATS*4)    // ~107.8 KB

typedef unsigned long long ULL;

// transposed+padded weights and bias, built once per launch by prep_kernel
__device__ float g_Wt[276480];
__device__ float g_bias[2432];
__device__ float g_part[NBLK];
__device__ unsigned int g_count;

// layer metadata: {w_in_idx, b_in_idx, CIN, COUT, KPAD, CW, woff, boff}
__constant__ int c_layers[15][8] = {
    { 1,  2, 165, 128, 176, 128,      0,    0},
    { 3,  4, 128, 256, 128, 256,  22528,  128},
    { 5,  6, 256, 256, 256, 256,  55296,  384},
    { 7,  8, 256,  32, 256,  32, 120832,  640},
    { 9, 10,  32, 256,  32, 256, 129024,  672},
    {11, 12, 256,  32, 256,  32, 137216,  928},
    {13, 14,  32, 256,  32, 256, 145408,  960},
    {15, 16, 256,  64, 256,  64, 153600, 1216},
    {18, 19,  64, 256,  64, 256, 169984, 1280},
    {20, 21, 256,  32, 256,  32, 186368, 1536},
    {22, 23,  32, 256,  32, 256, 194560, 1568},
    {24, 25, 256,  32, 256,  32, 202752, 1824},
    {26, 27,  32, 256,  32, 256, 210944, 1856},
    {28, 29, 256, 128, 256, 128, 219136, 2112},
    {30, 31, 128, 165, 128, 192, 251904, 2240},
};

// ---------------- f32x2 helpers ----------------
__device__ __forceinline__ ULL pack2(float x, float y) {
    ULL r; asm("mov.b64 %0, {%1, %2};" : "=l"(r) : "f"(x), "f"(y)); return r;
}
__device__ __forceinline__ void unpack2(ULL v, float& x, float& y) {
    asm("mov.b64 {%0, %1}, %2;" : "=f"(x), "=f"(y) : "l"(v));
}
__device__ __forceinline__ void fma2(ULL& d, ULL a, ULL b) {
    asm("fma.rn.f32x2 %0, %1, %2, %0;" : "+l"(d) : "l"(a), "l"(b));
}
__device__ __forceinline__ uint32_t smem_u32(const void* p) {
    uint32_t a;
    asm("{ .reg .u64 t; cvta.to.shared.u64 t, %1; cvt.u32.u64 %0, t; }" : "=r"(a) : "l"(p));
    return a;
}
__device__ __forceinline__ void cp_async16(uint32_t dst, const void* src) {
    asm volatile("cp.async.cg.shared.global [%0], [%1], 16;\n" :: "r"(dst), "l"(src));
}

// ---------------- prep: transpose + pad weights ----------------
struct Params { const float* in[32]; float* out; int out_size; };

__global__ void prep_kernel(Params P) {
    const int L = blockIdx.x;
    const int CIN  = c_layers[L][2], COUT = c_layers[L][3];
    const int KPAD = c_layers[L][4], CW   = c_layers[L][5];
    const int woff = c_layers[L][6], boff = c_layers[L][7];
    const float* W = P.in[c_layers[L][0]];
    const float* b = P.in[c_layers[L][1]];
    for (int e = threadIdx.x; e < KPAD * CW; e += blockDim.x) {
        int k = e / CW, c = e - (e / CW) * CW;
        float v = (k < CIN && c < COUT) ? W[c * CIN + k] : 0.f;
        g_Wt[woff + e] = v;
    }
    for (int c = threadIdx.x; c < CW; c += blockDim.x)
        g_bias[boff + c] = (c < COUT) ? b[c] : 0.f;
}

// ---------------- weight pair loads ----------------
// Alignment: base of wrow is (kk*CW + c0) floats from a 16B-aligned buffer.
// MT==8 -> c0 % 8 == 0 (32B), MT==4 -> c0 % 4 == 0 (16B): ulonglong2 OK.
// MT==6 -> c0 % 6 == 0, only 8B-aligned (e.g. c0=6): must use 8B ULL loads.
// MT==2 -> c0 % 2 == 0 (8B): ULL OK.
template<int MT>
__device__ __forceinline__ void load_wpairs(const float* wrow, ULL* wp) {
    if constexpr (MT == 8) {
        ulonglong2 q0 = *reinterpret_cast<const ulonglong2*>(wrow);
        ulonglong2 q1 = *reinterpret_cast<const ulonglong2*>(wrow + 4);
        wp[0] = q0.x; wp[1] = q0.y; wp[2] = q1.x; wp[3] = q1.y;
    }
    if constexpr (MT == 6) {
        wp[0] = *reinterpret_cast<const ULL*>(wrow);
        wp[1] = *reinterpret_cast<const ULL*>(wrow + 2);
        wp[2] = *reinterpret_cast<const ULL*>(wrow + 4);
    }
    if constexpr (MT == 4) {
        ulonglong2 q = *reinterpret_cast<const ulonglong2*>(wrow);
        wp[0] = q.x; wp[1] = q.y;
    }
    if constexpr (MT == 2) {
        wp[0] = *reinterpret_cast<const ULL*>(wrow);
    }
}

// ---------------- fused 1x1-conv layer ----------------
// OUT[c][t] = (RES? OUT[c][t]:0) + bias[c] + sum_k Wt[k][c] * (PRE? relu(IN[k][t]) : IN[k][t])
// 256 threads: 32 channel-groups (MT ch) x 8 token-groups (4 tokens)
template<int CW, int CINP, bool PRE, bool POST, bool RES>
__device__ __noinline__ void conv_layer(const float* __restrict__ Wt,
                                        const float* __restrict__ bias,
                                        const float* __restrict__ IN,
                                        float* __restrict__ OUT,
                                        float* __restrict__ Ws, int tid)
{
    constexpr int MT = CW / 32;
    constexpr int NK = CINP / KB;
    constexpr int PH = (MT >= 2) ? MT / 2 : 1;

    const int tx = tid & 7;
    const int ty = tid >> 3;
    const int j0 = tx * 4;
    const int c0 = ty * MT;

    float bv[MT];
#pragma unroll
    for (int m = 0; m < MT; m++) bv[m] = __ldg(bias + c0 + m);

    ULL acc[4][PH];
#pragma unroll
    for (int t = 0; t < 4; t++)
#pragma unroll
        for (int p = 0; p < PH; p++) acc[t][p] = 0ull;

    __syncthreads();   // prev-layer activations visible; Ws free

    // stage chunk 0 (linear memcpy of KB*CW floats)
    {
        const float4* src = reinterpret_cast<const float4*>(Wt);
        float4* dst = reinterpret_cast<float4*>(Ws);
        for (int i = tid; i < KB * CW / 4; i += THREADS)
            cp_async16(smem_u32(dst + i), src + i);
        asm volatile("cp.async.commit_group;\n" ::: "memory");
    }

    for (int kb = 0; kb < NK; kb++) {
        asm volatile("cp.async.wait_group 0;\n" ::: "memory");
        __syncthreads();
        if (kb + 1 < NK) {
            const float4* src = reinterpret_cast<const float4*>(Wt + (kb + 1) * KB * CW);
            float4* dst = reinterpret_cast<float4*>(Ws + ((kb + 1) & 1) * WBUFF);
            for (int i = tid; i < KB * CW / 4; i += THREADS)
                cp_async16(smem_u32(dst + i), src + i);
            asm volatile("cp.async.commit_group;\n" ::: "memory");
        }

        const float* Wk  = Ws + (kb & 1) * WBUFF;
        const float* inb = IN + kb * KB * LDA + j0;

        if constexpr (MT >= 2) {
#pragma unroll
            for (int kk = 0; kk < KB; kk++) {
                float4 v = *reinterpret_cast<const float4*>(inb + kk * LDA);
                if (PRE) {
                    v.x = fmaxf(v.x, 0.f); v.y = fmaxf(v.y, 0.f);
                    v.z = fmaxf(v.z, 0.f); v.w = fmaxf(v.w, 0.f);
                }
                ULL a0 = pack2(v.x, v.x), a1 = pack2(v.y, v.y);
                ULL a2 = pack2(v.z, v.z), a3 = pack2(v.w, v.w);
                ULL wp[PH];
                load_wpairs<MT>(Wk + kk * CW + c0, wp);
#pragma unroll
                for (int p = 0; p < PH; p++) {
                    fma2(acc[0][p], wp[p], a0);
                    fma2(acc[1][p], wp[p], a1);
                    fma2(acc[2][p], wp[p], a2);
                    fma2(acc[3][p], wp[p], a3);
                }
            }
        } else {
            // MT==1: token-pair orientation, scalar weight dup
#pragma unroll
            for (int kk = 0; kk < KB; kk++) {
                float4 v = *reinterpret_cast<const float4*>(inb + kk * LDA);
                if (PRE) {
                    v.x = fmaxf(v.x, 0.f); v.y = fmaxf(v.y, 0.f);
                    v.z = fmaxf(v.z, 0.f); v.w = fmaxf(v.w, 0.f);
                }
                ULL t0 = pack2(v.x, v.y), t1 = pack2(v.z, v.w);
                float w = Wk[kk * CW + c0];
                ULL wd = pack2(w, w);
                fma2(acc[0][0], wd, t0);
                fma2(acc[1][0], wd, t1);
            }
        }
    }

    // epilogue (no sync: OUT rows x token-quad owned exclusively; OUT != IN/Ws)
    if constexpr (MT >= 2) {
        float r[4][MT];
#pragma unroll
        for (int t = 0; t < 4; t++)
#pragma unroll
            for (int p = 0; p < PH; p++)
                unpack2(acc[t][p], r[t][2 * p], r[t][2 * p + 1]);
#pragma unroll
        for (int m = 0; m < MT; m++) {
            float4 o;
            o.x = r[0][m] + bv[m]; o.y = r[1][m] + bv[m];
            o.z = r[2][m] + bv[m]; o.w = r[3][m] + bv[m];
            float* op = OUT + (c0 + m) * LDA + j0;
            if (RES) {
                float4 e = *reinterpret_cast<float4*>(op);
                o.x += e.x; o.y += e.y; o.z += e.z; o.w += e.w;
            }
            if (POST) {
                o.x = fmaxf(o.x, 0.f); o.y = fmaxf(o.y, 0.f);
                o.z = fmaxf(o.z, 0.f); o.w = fmaxf(o.w, 0.f);
            }
            *reinterpret_cast<float4*>(op) = o;
        }
    } else {
        float4 o;
        unpack2(acc[0][0], o.x, o.y);
        unpack2(acc[1][0], o.z, o.w);
        o.x += bv[0]; o.y += bv[0]; o.z += bv[0]; o.w += bv[0];
        float* op = OUT + c0 * LDA + j0;
        if (RES) {
            float4 e = *reinterpret_cast<float4*>(op);
            o.x += e.x; o.y += e.y; o.z += e.z; o.w += e.w;
        }
        if (POST) {
            o.x = fmaxf(o.x, 0.f); o.y = fmaxf(o.y, 0.f);
            o.z = fmaxf(o.z, 0.f); o.w = fmaxf(o.w, 0.f);
        }
        *reinterpret_cast<float4*>(op) = o;
    }
}

#define LCONV(L, CW, CINP, PRE, POST, RES, INB, OUTB) \
    conv_layer<CW, CINP, PRE, POST, RES>(g_Wt + c_layers[L][6], g_bias + c_layers[L][7], INB, OUTB, Ws, tid)

// ---------------- main fused kernel ----------------
__global__ void __launch_bounds__(THREADS, 2) vqvae_kernel(Params P)
{
    extern __shared__ float sm[];
    float* A    = sm + SM_A;
    float* Bv   = sm + SM_B;
    float* Ws   = sm + SM_W;
    float* enp  = sm + SM_AUX;
    float* en   = enp + 256;
    float* wsum = en + 64;

    const int tid = threadIdx.x;
    const int n0  = blockIdx.x * TILE;

    // ---- load x tile: [tok][c] -> [c][tok]; zero-pad rows 165..175 ----
    const float* x = P.in[0];
    for (int idx = tid; idx < 176 * TILE; idx += THREADS) {
        int c = idx % 176;
        int j = idx / 176;
        A[c * LDA + j] = (c < CINN) ? x[(n0 + j) * CINN + c] : 0.f;
    }

    // ---- encoder ----
    LCONV(0, 128, 176, false, true,  false, A,  Bv);
    LCONV(1, 256, 128, false, true,  false, Bv, A );
    LCONV(2, 256, 256, false, false, false, A,  Bv);
    LCONV(3,  32, 256, true,  true,  false, Bv, A );
    LCONV(4, 256,  32, false, false, true,  A,  Bv);
    LCONV(5,  32, 256, true,  true,  false, Bv, A );
    LCONV(6, 256,  32, false, false, true,  A,  Bv);
    LCONV(7,  64, 256, true,  false, false, Bv, A );   // z -> A rows 0..63

    // ---- vector quantize (z lives in A rows 0..63) ----
    {
        const float* embed = P.in[17];
        float* Es = Ws;                 // [64 d][64 codes] = 16KB, fits in Ws
        const int j = tid >> 3;         // token 0..31
        const int q = tid & 7;          // code octet within 64-code block
        float best = 3.4e38f; int bidx = 0;

        for (int cb = 0; cb < 8; cb++) {
            __syncthreads();
            float sq = 0.f;
#pragma unroll
            for (int i = 0; i < 16; i++) {
                int idx = i * THREADS + tid;
                int kk = idx & 63, d = idx >> 6;
                float v = __ldg(embed + d * NEMB + cb * 64 + kk);
                Es[d * 64 + kk] = v;
                sq += v * v;            // all share kk = tid&63
            }
            enp[tid] = sq;
            __syncthreads();
            if (tid < 64)
                en[tid] = enp[tid] + enp[tid + 64] + enp[tid + 128] + enp[tid + 192];
            __syncthreads();

            ULL dot[4] = {0ull, 0ull, 0ull, 0ull};
#pragma unroll 8
            for (int d = 0; d < EDIM; d++) {
                float z = A[d * LDA + j];
                ULL z2 = pack2(z, z);
                const ulonglong2* er = reinterpret_cast<const ulonglong2*>(Es + d * 64 + q * 8);
                ulonglong2 e0 = er[0], e1 = er[1];
                fma2(dot[0], z2, e0.x); fma2(dot[1], z2, e0.y);
                fma2(dot[2], z2, e1.x); fma2(dot[3], z2, e1.y);
            }
#pragma unroll
            for (int g = 0; g < 4; g++) {
                float d0, d1; unpack2(dot[g], d0, d1);
                int kbv = cb * 64 + q * 8 + 2 * g;
                float s0 = en[q * 8 + 2 * g]     - 2.f * d0;
                float s1 = en[q * 8 + 2 * g + 1] - 2.f * d1;
                if (s0 < best) { best = s0; bidx = kbv; }
                if (s1 < best) { best = s1; bidx = kbv + 1; }
            }
        }
        // argmin across 8 lanes of this token (tie -> lower index)
#pragma unroll
        for (int off = 1; off < 8; off <<= 1) {
            float ob = __shfl_xor_sync(0xffffffffu, best, off);
            int   oi = __shfl_xor_sync(0xffffffffu, bidx, off);
            if (ob < best || (ob == best && oi < bidx)) { best = ob; bidx = oi; }
        }
        // gather codebook vector into A (in place), accumulate diff partial
        float dsum = 0.f;
#pragma unroll
        for (int dd = 0; dd < 8; dd++) {
            int d = q * 8 + dd;
            float e = __ldg(embed + d * NEMB + bidx);
            float z = A[d * LDA + j];
            A[d * LDA + j] = e;
            float df = e - z;
            dsum += df * df;
        }
#pragma unroll
        for (int off = 16; off > 0; off >>= 1)
            dsum += __shfl_xor_sync(0xffffffffu, dsum, off);
        if ((tid & 31) == 0) wsum[tid >> 5] = dsum;
        __syncthreads();
        if (tid == 0) {
            float s = 0.f;
#pragma unroll
            for (int w = 0; w < 8; w++) s += wsum[w];
            g_part[blockIdx.x] = s;
        }
    }

    // ---- decoder ----
    LCONV( 8, 256,  64, false, false, false, A,  Bv);
    LCONV( 9,  32, 256, true,  true,  false, Bv, A );
    LCONV(10, 256,  32, false, false, true,  A,  Bv);
    LCONV(11,  32, 256, true,  true,  false, Bv, A );
    LCONV(12, 256,  32, false, false, true,  A,  Bv);
    LCONV(13, 128, 256, true,  true,  false, Bv, A );
    LCONV(14, 192, 128, false, false, false, A,  Bv);
    __syncthreads();

    // ---- store output tile: [c][tok] -> [tok][c] ----
    for (int idx = tid; idx < CINN * TILE; idx += THREADS) {
        int j = idx / CINN;
        int c = idx - j * CINN;
        P.out[(n0 + j) * CINN + c] = Bv[c * LDA + j];
    }

    // ---- last-block finalize of diff ----
    __threadfence();
    __shared__ unsigned int is_last;
    if (tid == 0) is_last = (atomicAdd(&g_count, 1u) == NBLK - 1) ? 1u : 0u;
    __syncthreads();
    if (is_last) {
        float s = 0.f;
        for (int i = tid; i < NBLK; i += THREADS) s += g_part[i];
#pragma unroll
        for (int off = 16; off > 0; off >>= 1)
            s += __shfl_xor_sync(0xffffffffu, s, off);
        if ((tid & 31) == 0) wsum[tid >> 5] = s;
        __syncthreads();
        if (tid == 0) {
            float t = 0.f;
#pragma unroll
            for (int w = 0; w < 8; w++) t += wsum[w];
            if (P.out_size > DEC_ELEMS)
                P.out[DEC_ELEMS] = t * (1.0f / 8388608.0f);  // mean over N*EDIM
            g_count = 0u;   // reset for next graph replay
        }
    }
}

// ---------------- launch ----------------
extern "C" void kernel_launch(void* const* d_in, const int* in_sizes, int n_in,
                              void* d_out, int out_size)
{
    (void)in_sizes; (void)n_in;
    Params P;
    for (int i = 0; i < 32; i++) P.in[i] = (const float*)d_in[i];
    P.out = (float*)d_out;
    P.out_size = out_size;

    static bool attr_set = false;
    if (!attr_set) {
        cudaFuncSetAttribute(vqvae_kernel, cudaFuncAttributeMaxDynamicSharedMemorySize, SMEM_BYTES);
        attr_set = true;
    }
    prep_kernel<<<15, 256>>>(P);
    vqvae_kernel<<<NBLK, THREADS, SMEM_BYTES>>>(P);
}